// round 17
// baseline (speedup 1.0000x reference)
#include <cuda_runtime.h>
#include <cuda_fp16.h>
#include <math.h>

// ---------------- problem constants ----------------
#define MPTS   32768
#define NPTS   (MPTS * 8)          // 262144 upsampled points
#define NV     9
#define NC     24
#define NH     120
#define NW     160
#define CPRE   50
#define CIN    (NC + 1 + CPRE)     // 75
#define CHID   24
#define HW     (NH * NW)
#define VHW    (NV * HW)
#define VOXSZ  0.04f

#define KREAL  76                  // 75 inputs + bias-one
#define AST    86                  // shared row stride in halves (43 b32, odd -> conflict-free)
#define AST32  43

// ---------------- scratch (device globals; no allocation) ----------------
__device__ __align__(16) __half g_featTh[VHW * NC + 64];  // feats (V,H,W,C) fp16, +pad
__device__ __align__(16) float  g_features[NPTS * NC];    // per-point mean features
__device__ float  g_z[NPTS];
__device__ double g_red[3];                               // sum(z*pos), sum(z^2*pos), sum(pos)

__constant__ int c_off[8][3] = {
    {0,0,0},{1,0,0},{0,1,0},{0,0,1},{1,1,0},{1,0,1},{0,1,1},{1,1,1}
};

// ---------------- helpers ----------------
__device__ __forceinline__ __half2 u2h(unsigned u) {
    __half2 h;
    *reinterpret_cast<unsigned*>(&h) = u;
    return h;
}

// ---------------- kernel 1: transpose (V,C,H,W) fp32 -> (V,H,W,C) fp16; zero g_red ----------------
__global__ void k_transpose(const float* __restrict__ feats) {
    int tid = blockIdx.x * blockDim.x + threadIdx.x;
    if (tid == 0) { g_red[0] = 0.0; g_red[1] = 0.0; g_red[2] = 0.0; }
    if (tid >= VHW * 3) return;
    int pix = tid / 3;
    int c0  = (tid - pix * 3) * 8;
    int v   = pix / HW;
    int rem = pix - v * HW;
    const float* src = feats + (size_t)v * NC * HW + (size_t)c0 * HW + rem;
    float vals[8];
#pragma unroll
    for (int c = 0; c < 8; c++) vals[c] = src[(size_t)c * HW];
    __half2 h[4];
#pragma unroll
    for (int j = 0; j < 4; j++) h[j] = __floats2half2_rn(vals[2*j], vals[2*j+1]);
    reinterpret_cast<uint4*>(g_featTh)[pix * 3 + (c0 >> 3)] = *reinterpret_cast<uint4*>(h);
}

// ---------------- kernel 2: back-projection + per-point stats (R12 proven) ----------------
__global__ __launch_bounds__(256) void k_backproject(
    const int*   __restrict__ pre_coords,
    const float* __restrict__ KRcam,
    const float* __restrict__ origin,
    const float* __restrict__ w2ac,
    float*       __restrict__ d_out)
{
    __shared__ float sKR[NV * 16];
    __shared__ float sW2[12];
    __shared__ float sOrg[3];
    int t = threadIdx.x;
    if (t < NV * 16) sKR[t] = KRcam[t];
    if (t < 12)      sW2[t] = w2ac[t];
    if (t < 3)       sOrg[t] = origin[t];
    __syncthreads();

    int n = blockIdx.x * 256 + t;
    int m = n >> 3, k = n & 7;

    int cx = pre_coords[m * 4 + 1] + c_off[k][0];
    int cy = pre_coords[m * 4 + 2] + c_off[k][1];
    int cz = pre_coords[m * 4 + 3] + c_off[k][2];
    float wx = (float)cx * VOXSZ + sOrg[0];
    float wy = (float)cy * VOXSZ + sOrg[1];
    float wz = (float)cz * VOXSZ + sOrg[2];

    {
        float4 rc;
        rc.x = sW2[0]*wx + sW2[1]*wy + sW2[2]*wz + sW2[3];
        rc.y = sW2[4]*wx + sW2[5]*wy + sW2[6]*wz + sW2[7];
        rc.z = sW2[8]*wx + sW2[9]*wy + sW2[10]*wz + sW2[11];
        rc.w = 0.0f;
        reinterpret_cast<float4*>(d_out + 3 * NPTS)[n] = rc;
    }

    float a[NC];
#pragma unroll
    for (int j = 0; j < NC; j++) a[j] = 0.f;
    float zsum = 0.f;
    int   cnt  = 0;

    const uint4* fb = reinterpret_cast<const uint4*>(g_featTh);

#pragma unroll 1
    for (int v = 0; v < NV; v++) {
        const float* R = sKR + v * 16;
        float ix = R[0]*wx + R[1]*wy + R[2]*wz  + R[3];
        float iy = R[4]*wx + R[5]*wy + R[6]*wz  + R[7];
        float iz = R[8]*wx + R[9]*wy + R[10]*wz + R[11];
        float sz = (fabsf(iz) > 1e-9f) ? iz : 1e-9f;
        float px = ix / sz;
        float py = iy / sz;
        bool msk = (px >= 0.f) && (px <= (float)(NW - 1)) &&
                   (py >= 0.f) && (py <= (float)(NH - 1)) && (iz > 0.f);
        if (!msk) continue;

        float fx0 = floorf(px), fy0 = floorf(py);
        float ax = px - fx0,    ay = py - fy0;
        int ix0 = (int)fx0,     iy0 = (int)fy0;
        float okx = (ix0 + 1 < NW) ? 1.f : 0.f;
        float oky = (iy0 + 1 < NH) ? 1.f : 0.f;
        int iy1 = min(iy0 + 1, NH - 1);

        __half2 W00 = __float2half2_rn((1.f - ax) * (1.f - ay));
        __half2 W10 = __float2half2_rn(ax * (1.f - ay) * okx);
        __half2 W01 = __float2half2_rn((1.f - ax) * ay * oky);
        __half2 W11 = __float2half2_rn(ax * ay * okx * oky);

        int b_top = ((v * NH + iy0) * NW + ix0) * 3;
        int b_bot = ((v * NH + iy1) * NW + ix0) * 3;

#pragma unroll
        for (int j = 0; j < 3; j++) {
            uint4 T0 = fb[b_top + j];
            uint4 T1 = fb[b_top + j + 3];
            uint4 B0 = fb[b_bot + j];
            uint4 B1 = fb[b_bot + j + 3];
            int cb = 8 * j;
            __half2 r0 = __hmul2(u2h(T0.x), W00);
            r0 = __hfma2(u2h(T1.x), W10, r0);
            r0 = __hfma2(u2h(B0.x), W01, r0);
            r0 = __hfma2(u2h(B1.x), W11, r0);
            __half2 r1 = __hmul2(u2h(T0.y), W00);
            r1 = __hfma2(u2h(T1.y), W10, r1);
            r1 = __hfma2(u2h(B0.y), W01, r1);
            r1 = __hfma2(u2h(B1.y), W11, r1);
            __half2 r2 = __hmul2(u2h(T0.z), W00);
            r2 = __hfma2(u2h(T1.z), W10, r2);
            r2 = __hfma2(u2h(B0.z), W01, r2);
            r2 = __hfma2(u2h(B1.z), W11, r2);
            __half2 r3 = __hmul2(u2h(T0.w), W00);
            r3 = __hfma2(u2h(T1.w), W10, r3);
            r3 = __hfma2(u2h(B0.w), W01, r3);
            r3 = __hfma2(u2h(B1.w), W11, r3);
            float2 f0 = __half22float2(r0);
            float2 f1 = __half22float2(r1);
            float2 f2 = __half22float2(r2);
            float2 f3 = __half22float2(r3);
            a[cb+0] += f0.x;  a[cb+1] += f0.y;
            a[cb+2] += f1.x;  a[cb+3] += f1.y;
            a[cb+4] += f2.x;  a[cb+5] += f2.y;
            a[cb+6] += f3.x;  a[cb+7] += f3.y;
        }
        zsum += iz;
        cnt  += 1;
    }

    float denom = fmaxf((float)cnt, 1.f);
    float inv   = 1.f / denom;
    float4* fdst = reinterpret_cast<float4*>(g_features) + (size_t)n * 6;
#pragma unroll
    for (int j = 0; j < 6; j++)
        fdst[j] = make_float4(a[4*j]*inv, a[4*j+1]*inv, a[4*j+2]*inv, a[4*j+3]*inv);

    float zv = zsum * inv;
    g_z[n] = zv;
    d_out[2 * NPTS + n] = (float)cnt;

    bool  pos = zv > 0.f;
    float r0 = pos ? zv : 0.f;
    float r1 = pos ? zv * zv : 0.f;
    float r2 = pos ? 1.f : 0.f;
#pragma unroll
    for (int o = 16; o > 0; o >>= 1) {
        r0 += __shfl_down_sync(0xffffffffu, r0, o);
        r1 += __shfl_down_sync(0xffffffffu, r1, o);
        r2 += __shfl_down_sync(0xffffffffu, r2, o);
    }
    __shared__ float s0[8], s1[8], s2[8];
    int w = t >> 5, lane = t & 31;
    if (lane == 0) { s0[w] = r0; s1[w] = r1; s2[w] = r2; }
    __syncthreads();
    if (t == 0) {
        float t0 = 0.f, t1 = 0.f, t2 = 0.f;
#pragma unroll
        for (int i = 0; i < 8; i++) { t0 += s0[i]; t1 += s1[i]; t2 += s2[i]; }
        atomicAdd(&g_red[0], (double)t0);
        atomicAdd(&g_red[1], (double)t1);
        atomicAdd(&g_red[2], (double)t2);
    }
}

// ---------------- kernel 3: MLP via mma.sync m16n8k8 (fp16 in, fp32 accum) ----------------
// CTA = 256 threads / 256 points. A: [256][AST] halves. B: [24][AST] halves (B[n][k]).
// Warp w owns rows [32w, 32w+32): 2 m-tiles x 3 n-tiles x 10 k-steps = 60 HMMA.
__global__ __launch_bounds__(256) void k_mlp_mma(
    const float* __restrict__ pre_feat,
    const float* __restrict__ W_sp,
    const float* __restrict__ b_sp,
    const float* __restrict__ W_t,
    const float* __restrict__ b_t,
    const float* __restrict__ W_o,
    const float* __restrict__ b_o,
    float*       __restrict__ d_out)
{
    __shared__ __half sA[256 * AST];
    __shared__ __half sB[CHID * AST];
    __shared__ float  sWt[CHID], sWo[CHID];

    int tid = threadIdx.x;
    if (tid < CHID) { sWt[tid] = W_t[tid]; sWo[tid] = W_o[tid]; }

    // z normalization constants
    double npos  = fmax(g_red[2], 1.0);
    double zmean = g_red[0] / npos;
    double var   = g_red[1] - zmean * zmean * npos;
    float  znorm = (float)sqrt(fmax(var, 0.0)) + 1e-5f;
    float  zmf   = (float)zmean;

    int p_base = blockIdx.x * 256;
    int p0 = p_base + tid;

    // ---- stage A row (point p0 -> shared row tid) ----
    {
        float vals[KREAL];
        const float4* fs = reinterpret_cast<const float4*>(g_features) + (size_t)p0 * 6;
#pragma unroll
        for (int j = 0; j < 6; j++) {
            float4 f = fs[j];
            vals[4*j+0] = f.x; vals[4*j+1] = f.y; vals[4*j+2] = f.z; vals[4*j+3] = f.w;
        }
        float zv = g_z[p0];
        vals[NC] = (zv > 0.f) ? (zv - zmf) / znorm : 0.f;
        const float2* pf = reinterpret_cast<const float2*>(pre_feat + (size_t)(p0 >> 3) * CPRE);
#pragma unroll
        for (int i = 0; i < CPRE / 2; i++) {
            float2 g = pf[i];
            vals[NC + 1 + 2*i]     = g.x;
            vals[NC + 1 + 2*i + 1] = g.y;
        }
        vals[KREAL - 1] = 1.0f;                        // bias-one
        unsigned* row = reinterpret_cast<unsigned*>(sA) + tid * AST32;
#pragma unroll
        for (int i = 0; i < KREAL / 2; i++) {          // 38 b32
            __half2 h = __floats2half2_rn(vals[2*i], vals[2*i+1]);
            row[i] = *reinterpret_cast<unsigned*>(&h);
        }
#pragma unroll
        for (int i = KREAL / 2; i < AST32; i++) row[i] = 0;  // cols 76..85 zero
    }

    // ---- stage B: B[n][k] = W_sp[k][n], bias at k=75 ----
    for (int idx = tid; idx < CHID * AST32; idx += 256) {
        int nn = idx / AST32;
        int i  = idx - nn * AST32;
        int k0 = 2 * i, k1 = 2 * i + 1;
        float v0 = (k0 < CIN) ? W_sp[k0 * CHID + nn] : ((k0 == CIN) ? b_sp[nn] : 0.f);
        float v1 = (k1 < CIN) ? W_sp[k1 * CHID + nn] : ((k1 == CIN) ? b_sp[nn] : 0.f);
        __half2 h = __floats2half2_rn(v0, v1);
        reinterpret_cast<unsigned*>(sB)[nn * AST32 + i] = *reinterpret_cast<unsigned*>(&h);
    }
    __syncthreads();

    // ---- mma mainloop ----
    int w    = tid >> 5;
    int lane = tid & 31;
    int g    = lane >> 2;       // groupID (row within tile / n within B tile)
    int tig  = lane & 3;        // thread-in-group (k-pair / col-pair)

    float acc[2][3][4];
#pragma unroll
    for (int mt = 0; mt < 2; mt++)
#pragma unroll
        for (int j = 0; j < 3; j++)
#pragma unroll
            for (int q = 0; q < 4; q++) acc[mt][j][q] = 0.f;

    const unsigned* A32 = reinterpret_cast<const unsigned*>(sA);
    const unsigned* B32 = reinterpret_cast<const unsigned*>(sB);

#pragma unroll
    for (int s = 0; s < 10; s++) {                 // K = 80
        unsigned bf[3];
#pragma unroll
        for (int j = 0; j < 3; j++)                // B[n = j*8+g][k = tig*2 + s*8 ..+1]
            bf[j] = B32[(j * 8 + g) * AST32 + tig + s * 4];
#pragma unroll
        for (int mt = 0; mt < 2; mt++) {
            int r0 = w * 32 + mt * 16 + g;
            unsigned a0 = A32[r0 * AST32 + tig + s * 4];
            unsigned a1 = A32[(r0 + 8) * AST32 + tig + s * 4];
#pragma unroll
            for (int j = 0; j < 3; j++) {
                asm volatile(
                    "mma.sync.aligned.m16n8k8.row.col.f32.f16.f16.f32 "
                    "{%0,%1,%2,%3}, {%4,%5}, {%6}, {%0,%1,%2,%3};"
                    : "+f"(acc[mt][j][0]), "+f"(acc[mt][j][1]),
                      "+f"(acc[mt][j][2]), "+f"(acc[mt][j][3])
                    : "r"(a0), "r"(a1), "r"(bf[j]));
            }
        }
    }

    // ---- epilogue: relu + heads, reduce across the 4 lanes of each group ----
    float2* out = reinterpret_cast<float2*>(d_out);
#pragma unroll
    for (int mt = 0; mt < 2; mt++) {
        float tsA = 0.f, ocA = 0.f;   // row g
        float tsB = 0.f, ocB = 0.f;   // row g+8
#pragma unroll
        for (int j = 0; j < 3; j++) {
            int ch0 = j * 8 + tig * 2;
            float w0t = sWt[ch0], w1t = sWt[ch0 + 1];
            float w0o = sWo[ch0], w1o = sWo[ch0 + 1];
            float cA0 = fmaxf(acc[mt][j][0], 0.f), cA1 = fmaxf(acc[mt][j][1], 0.f);
            float cB0 = fmaxf(acc[mt][j][2], 0.f), cB1 = fmaxf(acc[mt][j][3], 0.f);
            tsA += cA0 * w0t + cA1 * w1t;  ocA += cA0 * w0o + cA1 * w1o;
            tsB += cB0 * w0t + cB1 * w1t;  ocB += cB0 * w0o + cB1 * w1o;
        }
#pragma unroll
        for (int o = 1; o <= 2; o <<= 1) {
            tsA += __shfl_xor_sync(0xffffffffu, tsA, o);
            ocA += __shfl_xor_sync(0xffffffffu, ocA, o);
            tsB += __shfl_xor_sync(0xffffffffu, tsB, o);
            ocB += __shfl_xor_sync(0xffffffffu, ocB, o);
        }
        if (tig == 0) {
            float bt = b_t[0], bo = b_o[0];
            int r = p_base + w * 32 + mt * 16 + g;
            out[r]     = make_float2(tsA + bt, ocA + bo);
            out[r + 8] = make_float2(tsB + bt, ocB + bo);
        }
    }
}

// ---------------- launch ----------------
extern "C" void kernel_launch(void* const* d_in, const int* in_sizes, int n_in,
                              void* d_out, int out_size)
{
    const float *pre_feat = nullptr, *feats = nullptr, *KRcam = nullptr,
                *origin = nullptr, *w2ac = nullptr, *W_sp = nullptr,
                *b_sp = nullptr, *W_t = nullptr, *b_t = nullptr,
                *W_o = nullptr, *b_o = nullptr;
    const int* pre_coords = nullptr;
    int n24 = 0, n1 = 0;

    for (int i = 0; i < n_in; i++) {
        int s = in_sizes[i];
        const void* p = d_in[i];
        switch (s) {
            case MPTS * CPRE:  pre_feat   = (const float*)p; break;
            case MPTS * 4:     pre_coords = (const int*)p;   break;
            case VHW * NC:     feats      = (const float*)p; break;
            case NV * 16:      KRcam      = (const float*)p; break;
            case 3:            origin     = (const float*)p; break;
            case 16:           w2ac       = (const float*)p; break;
            case CIN * CHID:   W_sp       = (const float*)p; break;
            case 24:
                if (n24 == 0) b_sp = (const float*)p;
                else if (n24 == 1) W_t = (const float*)p;
                else W_o = (const float*)p;
                n24++; break;
            case 1:
                if (n1 == 0) b_t = (const float*)p;
                else b_o = (const float*)p;
                n1++; break;
            default: break;
        }
    }

    k_transpose<<<(VHW * 3 + 255) / 256, 256>>>(feats);
    k_backproject<<<NPTS / 256, 256>>>(pre_coords, KRcam, origin, w2ac, (float*)d_out);
    k_mlp_mma<<<NPTS / 256, 256>>>(pre_feat, W_sp, b_sp, W_t, b_t, W_o, b_o, (float*)d_out);
}